// round 1
// baseline (speedup 1.0000x reference)
#include <cuda_runtime.h>

#define BB 16
#define T_STEPS 20

// ---------------- persistent device state ----------------
__device__ float g_v [BB*3*32*32];
__device__ float g_s [BB*3*32*32];
__device__ float g_m1[BB*64*32*32];
__device__ float g_o1[BB*64*32*32];
__device__ float g_o1p[BB*64*16*16];
__device__ float g_m2[BB*128*16*16];
__device__ float g_o2[BB*128*16*16];
__device__ float g_m3[BB*128*16*16];
__device__ float g_o3[BB*128*16*16];
__device__ float g_f [BB*8192];
__device__ float g_m4[BB*1024];
__device__ float g_o4[BB*1024];
__device__ float g_m5[BB*1024];
__device__ float g_o5[BB*1024];
__device__ float g_mo[BB*10];

// ---------------- zero state ----------------
__global__ void zero_state() {
    int n  = gridDim.x * blockDim.x;
    int i0 = blockIdx.x * blockDim.x + threadIdx.x;
    for (int i = i0; i < BB*3*32*32;   i += n) { g_v[i] = 0.f; g_s[i] = 0.f; }
    for (int i = i0; i < BB*64*32*32;  i += n)   g_m1[i] = 0.f;
    for (int i = i0; i < BB*128*16*16; i += n) { g_m2[i] = 0.f; g_m3[i] = 0.f; }
    for (int i = i0; i < BB*1024;      i += n) { g_m4[i] = 0.f; g_m5[i] = 0.f; }
    for (int i = i0; i < BB*10;        i += n)   g_mo[i] = 0.f;
}

// ---------------- per-step spike / threshold kernel ----------------
// All layer spikes depend only on previous-step membranes, so they all
// compute here in one elementwise kernel. Membranes are NOT modified here;
// the GEMM kernel does m = (m + inp) - out to match reference rounding order.
__global__ void __launch_bounds__(256) spike_step(const float* __restrict__ x) {
    int i = blockIdx.x * 256 + threadIdx.x;
    if (i < 49152) {
        // encoder: v = (v + x) - s_prev ; s = (v > 1)
        float v = g_v[i] + x[i];
        v = v - g_s[i];
        g_v[i] = v;
        g_s[i] = (v > 1.0f) ? 1.0f : 0.0f;
    } else if (i < 311296) {
        // conv1 spikes + 2x2 avg pool : one thread per pooled output
        int p  = i - 49152;                 // over (B*64, 16, 16)
        int px = p & 15, py = (p >> 4) & 15, bc = p >> 8;
        int base = (bc*32 + py*2)*32 + px*2;
        float sum = 0.f;
        #pragma unroll
        for (int dy = 0; dy < 2; dy++)
            #pragma unroll
            for (int dx = 0; dx < 2; dx++) {
                int idx = base + dy*32 + dx;
                float o = (g_m1[idx] > 1.0f) ? 1.0f : 0.0f;
                g_o1[idx] = o;
                sum += o;
            }
        g_o1p[p] = sum * 0.25f;
    } else if (i < 835584) {
        int p = i - 311296;
        g_o2[p] = (g_m2[p] > 1.0f) ? 1.0f : 0.0f;
    } else if (i < 966656) {
        // conv3 spikes + pool -> flattened f
        int p  = i - 835584;                // over (B*128, 8, 8)
        int px = p & 7, py = (p >> 3) & 7, bc = p >> 6;
        int base = (bc*16 + py*2)*16 + px*2;
        float sum = 0.f;
        #pragma unroll
        for (int dy = 0; dy < 2; dy++)
            #pragma unroll
            for (int dx = 0; dx < 2; dx++) {
                int idx = base + dy*16 + dx;
                float o = (g_m3[idx] > 1.0f) ? 1.0f : 0.0f;
                g_o3[idx] = o;
                sum += o;
            }
        int b = bc >> 7, c = bc & 127;
        g_f[b*8192 + c*64 + py*8 + px] = sum * 0.25f;
    } else if (i < 983040) {
        int p = i - 966656;
        g_o4[p] = (g_m4[p] > 1.0f) ? 1.0f : 0.0f;
    } else if (i < 999424) {
        int p = i - 983040;
        g_o5[p] = (g_m5[p] > 1.0f) ? 1.0f : 0.0f;
    }
}

// ---------------- conv (16x16 spatial, 3x3 SAME, 128 out-ch total) ----------------
// block: one batch b, 16 out-channels. per thread: 2 oc x 8 px. smem tiles of 16 in-ch.
__device__ __forceinline__ void conv16x16(
    const float* __restrict__ in, const float* __restrict__ W,
    float* __restrict__ m, const float* __restrict__ osp,
    int CIN, int b, int oc0, float* sm)
{
    float* in_s = sm;         // [16][18][20] = 5760
    float* w_s  = sm + 5760;  // [16][144]    = 2304
    int tid = threadIdx.x;
    int ol0 = (tid >> 5) * 2;       // local oc pair
    int sg  = tid & 31;
    int y   = sg >> 1;
    int xb  = (sg & 1) * 8;

    float acc[2][8];
    #pragma unroll
    for (int q = 0; q < 2; q++)
        #pragma unroll
        for (int i = 0; i < 8; i++) acc[q][i] = 0.f;

    for (int cb = 0; cb < CIN; cb += 16) {
        __syncthreads();
        for (int idx = tid; idx < 5760; idx += 256) {
            int c  = idx / 360; int r = idx - c*360;
            int yy = r / 20;    int xx = r - yy*20;
            int gy = yy - 1, gx = xx - 1;
            float v = 0.f;
            if ((unsigned)gy < 16u && (unsigned)gx < 16u)
                v = in[((b*CIN + cb + c)*16 + gy)*16 + gx];
            in_s[idx] = v;
        }
        for (int idx = tid; idx < 2304; idx += 256) {
            int ol = idx / 144; int t = idx - ol*144;
            w_s[ol*144 + t] = W[(oc0 + ol)*CIN*9 + cb*9 + t];
        }
        __syncthreads();
        #pragma unroll 1
        for (int c = 0; c < 16; c++) {
            #pragma unroll
            for (int dy = 0; dy < 3; dy++) {
                const float* row = in_s + c*360 + (y + dy)*20 + xb;
                float iv[11];
                #pragma unroll
                for (int t = 0; t < 11; t++) iv[t] = row[t];
                float w0[3], w1[3];
                #pragma unroll
                for (int dx = 0; dx < 3; dx++) {
                    w0[dx] = w_s[ ol0     *144 + c*9 + dy*3 + dx];
                    w1[dx] = w_s[(ol0 + 1)*144 + c*9 + dy*3 + dx];
                }
                #pragma unroll
                for (int i = 0; i < 8; i++)
                    #pragma unroll
                    for (int dx = 0; dx < 3; dx++) {
                        acc[0][i] += iv[i + dx] * w0[dx];
                        acc[1][i] += iv[i + dx] * w1[dx];
                    }
            }
        }
    }
    #pragma unroll
    for (int q = 0; q < 2; q++) {
        int oc   = oc0 + ol0 + q;
        int base = ((b*128 + oc)*16 + y)*16 + xb;
        #pragma unroll
        for (int i = 0; i < 8; i++) {
            int idx = base + i;
            m[idx] = (m[idx] + acc[q][i]) - osp[idx];
        }
    }
}

// ---------------- conv1 (3 in-ch, 32x32), naive with smem weights ----------------
__device__ __forceinline__ void conv1_part(
    const float* __restrict__ s, const float* __restrict__ W1,
    float* __restrict__ m1, const float* __restrict__ o1,
    int cblk, float* sm)
{
    int tid = threadIdx.x;
    for (int idx = tid; idx < 1728; idx += 256) sm[idx] = W1[idx];
    __syncthreads();
    int u   = cblk*256 + tid;
    int row = u >> 2;
    int xb  = (u & 3) * 8;
    int b   = row >> 11;
    int oc  = (row >> 5) & 63;
    int y   = row & 31;
    float acc[8];
    #pragma unroll
    for (int i = 0; i < 8; i++) acc[i] = 0.f;
    #pragma unroll
    for (int c = 0; c < 3; c++) {
        #pragma unroll
        for (int dy = 0; dy < 3; dy++) {
            int gy = y + dy - 1;
            if ((unsigned)gy >= 32u) continue;
            const float* srow = s + ((b*3 + c)*32 + gy)*32;
            float iv[10];
            #pragma unroll
            for (int t = 0; t < 10; t++) {
                int gx = xb + t - 1;
                iv[t] = ((unsigned)gx < 32u) ? srow[gx] : 0.f;
            }
            float w[3];
            #pragma unroll
            for (int dx = 0; dx < 3; dx++) w[dx] = sm[oc*27 + c*9 + dy*3 + dx];
            #pragma unroll
            for (int i = 0; i < 8; i++)
                #pragma unroll
                for (int dx = 0; dx < 3; dx++)
                    acc[i] += iv[i + dx] * w[dx];
        }
    }
    int base = ((b*64 + oc)*32 + y)*32 + xb;
    #pragma unroll
    for (int i = 0; i < 8; i++) {
        int idx = base + i;
        m1[idx] = (m1[idx] + acc[i]) - o1[idx];
    }
}

// ---------------- FC: out[b,j] += A[b,:] . W[j,:] ----------------
// block: 64 j x 16 b. per thread 2j x 2b register tile (4 LDS : 4 FFMA).
__device__ __forceinline__ void fc_part(
    const float* __restrict__ A, const float* __restrict__ W,
    float* __restrict__ M, const float* __restrict__ O,
    int K, int J, int j0, int k0, int KS, bool subO, float* sm)
{
    float* fs = sm;          // [16][64]
    float* ws = sm + 1024;   // [64][65]
    int tid = threadIdx.x;
    int tj  = tid & 31;
    int tb  = tid >> 5;
    float acc[2][2] = {{0.f,0.f},{0.f,0.f}};
    for (int kc = k0; kc < k0 + KS; kc += 64) {
        __syncthreads();
        for (int idx = tid; idx < 1024; idx += 256) {
            int bb = idx >> 6, kk = idx & 63;
            fs[idx] = A[bb*K + kc + kk];
        }
        for (int idx = tid; idx < 4096; idx += 256) {
            int jl = idx >> 6, kk = idx & 63;
            ws[jl*65 + kk] = W[(j0 + jl)*K + kc + kk];
        }
        __syncthreads();
        #pragma unroll 4
        for (int kk = 0; kk < 64; kk++) {
            float w0 = ws[(tj*2    )*65 + kk];
            float w1 = ws[(tj*2 + 1)*65 + kk];
            float f0 = fs[ tb      *64 + kk];
            float f1 = fs[(tb + 8) *64 + kk];
            acc[0][0] += w0*f0;  acc[0][1] += w0*f1;
            acc[1][0] += w1*f0;  acc[1][1] += w1*f1;
        }
    }
    #pragma unroll
    for (int q = 0; q < 2; q++)
        #pragma unroll
        for (int r = 0; r < 2; r++) {
            int j  = j0 + tj*2 + q;
            int bb = tb + r*8;
            int idx = bb*J + j;
            float val = acc[q][r];
            if (subO) val -= O[idx];
            atomicAdd(&M[idx], val);
        }
}

// ---------------- fc3: mo += o5 @ L3^T (tiny) ----------------
__device__ __forceinline__ void fc3_part(
    const float* __restrict__ o5, const float* __restrict__ L3, float* __restrict__ mo)
{
    int t = threadIdx.x;
    if (t >= 160) return;
    int b = t / 10, j = t - b*10;
    const float* a = o5 + b*1024;
    const float* w = L3 + j*1024;
    float acc = 0.f;
    #pragma unroll 4
    for (int k = 0; k < 1024; k++) acc += a[k]*w[k];
    mo[t] += acc;
}

// ---------------- fat per-step GEMM kernel: all layers run concurrently ----------------
__global__ void __launch_bounds__(256) conv_step(
    const float* __restrict__ W1, const float* __restrict__ W2,
    const float* __restrict__ W3, const float* __restrict__ L1,
    const float* __restrict__ L2, const float* __restrict__ L3)
{
    __shared__ float sm[8256];
    int blk = blockIdx.x;
    if (blk < 128) {                       // conv3 (biggest first)
        conv16x16(g_o2, W3, g_m3, g_o3, 128, blk >> 3, (blk & 7)*16, sm);
    } else if (blk < 256) {                // conv2
        int i = blk - 128;
        conv16x16(g_o1p, W2, g_m2, g_o2, 64, i >> 3, (i & 7)*16, sm);
    } else if (blk < 288) {                // fc1 (K split in 2, atomic accumulate)
        int i = blk - 256;
        int ks = i >> 4, jg = i & 15;
        fc_part(g_f, L1, g_m4, g_o4, 8192, 1024, jg*64, ks*4096, 4096, ks == 0, sm);
    } else if (blk < 304) {                // fc2
        int i = blk - 288;
        fc_part(g_o4, L2, g_m5, g_o5, 1024, 1024, i*64, 0, 1024, true, sm);
    } else if (blk < 816) {                // conv1
        conv1_part(g_s, W1, g_m1, g_o1, blk - 304, sm);
    } else {                               // fc3
        fc3_part(g_o5, L3, g_mo);
    }
}

__global__ void write_out(float* __restrict__ out) {
    int t = threadIdx.x;
    if (t < 160) out[t] = g_mo[t];
}

extern "C" void kernel_launch(void* const* d_in, const int* in_sizes, int n_in,
                              void* d_out, int out_size)
{
    const float* x  = (const float*)d_in[0];
    const float* W1 = (const float*)d_in[1];
    const float* W2 = (const float*)d_in[2];
    const float* W3 = (const float*)d_in[3];
    const float* L1 = (const float*)d_in[4];
    const float* L2 = (const float*)d_in[5];
    const float* L3 = (const float*)d_in[6];

    zero_state<<<512, 256>>>();
    for (int t = 0; t < T_STEPS; t++) {
        spike_step<<<3904, 256>>>(x);
        conv_step<<<817, 256>>>(W1, W2, W3, L1, L2, L3);
    }
    write_out<<<1, 192>>>((float*)d_out);
}

// round 2
// speedup vs baseline: 1.0051x; 1.0051x over previous
#include <cuda_runtime.h>

#define BB 16
#define T_STEPS 20

// ---------------- persistent device state ----------------
__device__ float g_v [BB*3*32*32];
__device__ float g_s [BB*3*32*32];
__device__ float g_m1[BB*64*32*32];
__device__ float g_o1[BB*64*32*32];
__device__ float g_o1p[BB*64*16*16];
__device__ float g_m2[BB*128*16*16];
__device__ float g_o2[BB*128*16*16];
__device__ float g_m3[BB*128*16*16];
__device__ float g_o3[BB*128*16*16];
__device__ float g_f [BB*8192];
__device__ float g_m4[BB*1024];
__device__ float g_o4[BB*1024];
__device__ float g_m5[BB*1024];
__device__ float g_o5[BB*1024];
__device__ float g_mo[BB*10];

// ---------------- zero state ----------------
__global__ void zero_state() {
    int n  = gridDim.x * blockDim.x;
    int i0 = blockIdx.x * blockDim.x + threadIdx.x;
    for (int i = i0; i < BB*3*32*32;   i += n) { g_v[i] = 0.f; g_s[i] = 0.f; }
    for (int i = i0; i < BB*64*32*32;  i += n)   g_m1[i] = 0.f;
    for (int i = i0; i < BB*128*16*16; i += n) { g_m2[i] = 0.f; g_m3[i] = 0.f; }
    for (int i = i0; i < BB*1024;      i += n) { g_m4[i] = 0.f; g_m5[i] = 0.f; }
    for (int i = i0; i < BB*10;        i += n)   g_mo[i] = 0.f;
}

// ---------------- per-step spike / threshold kernel ----------------
// All layer spikes depend only on previous-step membranes, so they all
// compute here in one elementwise kernel. Membranes are NOT modified here;
// the GEMM kernel does m = (m + inp) - out to match reference rounding order.
__global__ void __launch_bounds__(256) spike_step(const float* __restrict__ x) {
    int i = blockIdx.x * 256 + threadIdx.x;
    if (i < 49152) {
        // encoder: v = (v + x) - s_prev ; s = (v > 1)
        float v = g_v[i] + x[i];
        v = v - g_s[i];
        g_v[i] = v;
        g_s[i] = (v > 1.0f) ? 1.0f : 0.0f;
    } else if (i < 311296) {
        // conv1 spikes + 2x2 avg pool : one thread per pooled output
        int p  = i - 49152;                 // over (B*64, 16, 16)
        int px = p & 15, py = (p >> 4) & 15, bc = p >> 8;
        int base = (bc*32 + py*2)*32 + px*2;
        float sum = 0.f;
        #pragma unroll
        for (int dy = 0; dy < 2; dy++)
            #pragma unroll
            for (int dx = 0; dx < 2; dx++) {
                int idx = base + dy*32 + dx;
                float o = (g_m1[idx] > 1.0f) ? 1.0f : 0.0f;
                g_o1[idx] = o;
                sum += o;
            }
        g_o1p[p] = sum * 0.25f;
    } else if (i < 835584) {
        int p = i - 311296;
        g_o2[p] = (g_m2[p] > 1.0f) ? 1.0f : 0.0f;
    } else if (i < 966656) {
        // conv3 spikes + pool -> flattened f
        int p  = i - 835584;                // over (B*128, 8, 8)
        int px = p & 7, py = (p >> 3) & 7, bc = p >> 6;
        int base = (bc*16 + py*2)*16 + px*2;
        float sum = 0.f;
        #pragma unroll
        for (int dy = 0; dy < 2; dy++)
            #pragma unroll
            for (int dx = 0; dx < 2; dx++) {
                int idx = base + dy*16 + dx;
                float o = (g_m3[idx] > 1.0f) ? 1.0f : 0.0f;
                g_o3[idx] = o;
                sum += o;
            }
        int b = bc >> 7, c = bc & 127;
        g_f[b*8192 + c*64 + py*8 + px] = sum * 0.25f;
    } else if (i < 983040) {
        int p = i - 966656;
        g_o4[p] = (g_m4[p] > 1.0f) ? 1.0f : 0.0f;
    } else if (i < 999424) {
        int p = i - 983040;
        g_o5[p] = (g_m5[p] > 1.0f) ? 1.0f : 0.0f;
    }
}

// ---------------- conv (16x16 spatial, 3x3 SAME, 128 out-ch total) ----------------
// block: one batch b, 16 out-channels. per thread: 2 oc x 8 px. smem tiles of 16 in-ch.
__device__ __forceinline__ void conv16x16(
    const float* __restrict__ in, const float* __restrict__ W,
    float* __restrict__ m, const float* __restrict__ osp,
    int CIN, int b, int oc0, float* sm)
{
    float* in_s = sm;         // [16][18][20] = 5760
    float* w_s  = sm + 5760;  // [16][144]    = 2304
    int tid = threadIdx.x;
    int ol0 = (tid >> 5) * 2;       // local oc pair
    int sg  = tid & 31;
    int y   = sg >> 1;
    int xb  = (sg & 1) * 8;

    float acc[2][8];
    #pragma unroll
    for (int q = 0; q < 2; q++)
        #pragma unroll
        for (int i = 0; i < 8; i++) acc[q][i] = 0.f;

    for (int cb = 0; cb < CIN; cb += 16) {
        __syncthreads();
        for (int idx = tid; idx < 5760; idx += 256) {
            int c  = idx / 360; int r = idx - c*360;
            int yy = r / 20;    int xx = r - yy*20;
            int gy = yy - 1, gx = xx - 1;
            float v = 0.f;
            if ((unsigned)gy < 16u && (unsigned)gx < 16u)
                v = in[((b*CIN + cb + c)*16 + gy)*16 + gx];
            in_s[idx] = v;
        }
        for (int idx = tid; idx < 2304; idx += 256) {
            int ol = idx / 144; int t = idx - ol*144;
            w_s[ol*144 + t] = W[(oc0 + ol)*CIN*9 + cb*9 + t];
        }
        __syncthreads();
        #pragma unroll 1
        for (int c = 0; c < 16; c++) {
            #pragma unroll
            for (int dy = 0; dy < 3; dy++) {
                const float* row = in_s + c*360 + (y + dy)*20 + xb;
                float iv[11];
                #pragma unroll
                for (int t = 0; t < 11; t++) iv[t] = row[t];
                float w0[3], w1[3];
                #pragma unroll
                for (int dx = 0; dx < 3; dx++) {
                    w0[dx] = w_s[ ol0     *144 + c*9 + dy*3 + dx];
                    w1[dx] = w_s[(ol0 + 1)*144 + c*9 + dy*3 + dx];
                }
                #pragma unroll
                for (int i = 0; i < 8; i++)
                    #pragma unroll
                    for (int dx = 0; dx < 3; dx++) {
                        acc[0][i] += iv[i + dx] * w0[dx];
                        acc[1][i] += iv[i + dx] * w1[dx];
                    }
            }
        }
    }
    #pragma unroll
    for (int q = 0; q < 2; q++) {
        int oc   = oc0 + ol0 + q;
        int base = ((b*128 + oc)*16 + y)*16 + xb;
        #pragma unroll
        for (int i = 0; i < 8; i++) {
            int idx = base + i;
            m[idx] = (m[idx] + acc[q][i]) - osp[idx];
        }
    }
}

// ---------------- conv1 (3 in-ch, 32x32), naive with smem weights ----------------
__device__ __forceinline__ void conv1_part(
    const float* __restrict__ s, const float* __restrict__ W1,
    float* __restrict__ m1, const float* __restrict__ o1,
    int cblk, float* sm)
{
    int tid = threadIdx.x;
    for (int idx = tid; idx < 1728; idx += 256) sm[idx] = W1[idx];
    __syncthreads();
    int u   = cblk*256 + tid;
    int row = u >> 2;
    int xb  = (u & 3) * 8;
    int b   = row >> 11;
    int oc  = (row >> 5) & 63;
    int y   = row & 31;
    float acc[8];
    #pragma unroll
    for (int i = 0; i < 8; i++) acc[i] = 0.f;
    #pragma unroll
    for (int c = 0; c < 3; c++) {
        #pragma unroll
        for (int dy = 0; dy < 3; dy++) {
            int gy = y + dy - 1;
            if ((unsigned)gy >= 32u) continue;
            const float* srow = s + ((b*3 + c)*32 + gy)*32;
            float iv[10];
            #pragma unroll
            for (int t = 0; t < 10; t++) {
                int gx = xb + t - 1;
                iv[t] = ((unsigned)gx < 32u) ? srow[gx] : 0.f;
            }
            float w[3];
            #pragma unroll
            for (int dx = 0; dx < 3; dx++) w[dx] = sm[oc*27 + c*9 + dy*3 + dx];
            #pragma unroll
            for (int i = 0; i < 8; i++)
                #pragma unroll
                for (int dx = 0; dx < 3; dx++)
                    acc[i] += iv[i + dx] * w[dx];
        }
    }
    int base = ((b*64 + oc)*32 + y)*32 + xb;
    #pragma unroll
    for (int i = 0; i < 8; i++) {
        int idx = base + i;
        m1[idx] = (m1[idx] + acc[i]) - o1[idx];
    }
}

// ---------------- FC: out[b,j] += A[b,:] . W[j,:] ----------------
// block: 64 j x 16 b. per thread 2j x 2b register tile (4 LDS : 4 FFMA).
__device__ __forceinline__ void fc_part(
    const float* __restrict__ A, const float* __restrict__ W,
    float* __restrict__ M, const float* __restrict__ O,
    int K, int J, int j0, int k0, int KS, bool subO, float* sm)
{
    float* fs = sm;          // [16][64]
    float* ws = sm + 1024;   // [64][65]
    int tid = threadIdx.x;
    int tj  = tid & 31;
    int tb  = tid >> 5;
    float acc[2][2] = {{0.f,0.f},{0.f,0.f}};
    for (int kc = k0; kc < k0 + KS; kc += 64) {
        __syncthreads();
        for (int idx = tid; idx < 1024; idx += 256) {
            int bb = idx >> 6, kk = idx & 63;
            fs[idx] = A[bb*K + kc + kk];
        }
        for (int idx = tid; idx < 4096; idx += 256) {
            int jl = idx >> 6, kk = idx & 63;
            ws[jl*65 + kk] = W[(j0 + jl)*K + kc + kk];
        }
        __syncthreads();
        #pragma unroll 4
        for (int kk = 0; kk < 64; kk++) {
            float w0 = ws[(tj*2    )*65 + kk];
            float w1 = ws[(tj*2 + 1)*65 + kk];
            float f0 = fs[ tb      *64 + kk];
            float f1 = fs[(tb + 8) *64 + kk];
            acc[0][0] += w0*f0;  acc[0][1] += w0*f1;
            acc[1][0] += w1*f0;  acc[1][1] += w1*f1;
        }
    }
    #pragma unroll
    for (int q = 0; q < 2; q++)
        #pragma unroll
        for (int r = 0; r < 2; r++) {
            int j  = j0 + tj*2 + q;
            int bb = tb + r*8;
            int idx = bb*J + j;
            float val = acc[q][r];
            if (subO) val -= O[idx];
            atomicAdd(&M[idx], val);
        }
}

// ---------------- fc3: mo += o5 @ L3^T (tiny) ----------------
__device__ __forceinline__ void fc3_part(
    const float* __restrict__ o5, const float* __restrict__ L3, float* __restrict__ mo)
{
    int t = threadIdx.x;
    if (t >= 160) return;
    int b = t / 10, j = t - b*10;
    const float* a = o5 + b*1024;
    const float* w = L3 + j*1024;
    float acc = 0.f;
    #pragma unroll 4
    for (int k = 0; k < 1024; k++) acc += a[k]*w[k];
    mo[t] += acc;
}

// ---------------- fat per-step GEMM kernel: all layers run concurrently ----------------
__global__ void __launch_bounds__(256) conv_step(
    const float* __restrict__ W1, const float* __restrict__ W2,
    const float* __restrict__ W3, const float* __restrict__ L1,
    const float* __restrict__ L2, const float* __restrict__ L3)
{
    __shared__ float sm[8256];
    int blk = blockIdx.x;
    if (blk < 128) {                       // conv3 (biggest first)
        conv16x16(g_o2, W3, g_m3, g_o3, 128, blk >> 3, (blk & 7)*16, sm);
    } else if (blk < 256) {                // conv2
        int i = blk - 128;
        conv16x16(g_o1p, W2, g_m2, g_o2, 64, i >> 3, (i & 7)*16, sm);
    } else if (blk < 288) {                // fc1 (K split in 2, atomic accumulate)
        int i = blk - 256;
        int ks = i >> 4, jg = i & 15;
        fc_part(g_f, L1, g_m4, g_o4, 8192, 1024, jg*64, ks*4096, 4096, ks == 0, sm);
    } else if (blk < 304) {                // fc2
        int i = blk - 288;
        fc_part(g_o4, L2, g_m5, g_o5, 1024, 1024, i*64, 0, 1024, true, sm);
    } else if (blk < 816) {                // conv1
        conv1_part(g_s, W1, g_m1, g_o1, blk - 304, sm);
    } else {                               // fc3
        fc3_part(g_o5, L3, g_mo);
    }
}

__global__ void write_out(float* __restrict__ out) {
    int t = threadIdx.x;
    if (t < 160) out[t] = g_mo[t];
}

extern "C" void kernel_launch(void* const* d_in, const int* in_sizes, int n_in,
                              void* d_out, int out_size)
{
    const float* x  = (const float*)d_in[0];
    const float* W1 = (const float*)d_in[1];
    const float* W2 = (const float*)d_in[2];
    const float* W3 = (const float*)d_in[3];
    const float* L1 = (const float*)d_in[4];
    const float* L2 = (const float*)d_in[5];
    const float* L3 = (const float*)d_in[6];

    zero_state<<<512, 256>>>();
    for (int t = 0; t < T_STEPS; t++) {
        spike_step<<<3904, 256>>>(x);
        conv_step<<<817, 256>>>(W1, W2, W3, L1, L2, L3);
    }
    write_out<<<1, 192>>>((float*)d_out);
}

// round 3
// speedup vs baseline: 1.3738x; 1.3668x over previous
#include <cuda_runtime.h>
#include <cstdint>

#define BB 16
#define T_STEPS 20
#define NT 657

// ---------------- persistent device state ----------------
__device__ float g_v [BB*3*32*32];
__device__ float g_s [BB*3*32*32];
__device__ float g_m1[BB*64*32*32];
__device__ float g_o1[BB*64*32*32];
__device__ float g_o1p[BB*64*16*16];
__device__ float g_m2[BB*128*16*16];
__device__ float g_o2[BB*128*16*16];
__device__ float g_m3[BB*128*16*16];
__device__ float g_o3[BB*128*16*16];
__device__ float g_f [BB*8192];
__device__ float g_m4[BB*1024];
__device__ float g_o4[BB*1024];
__device__ float g_m5[BB*1024];
__device__ float g_o5[BB*1024];
__device__ float g_mo[BB*10];
__device__ int   g_tick;

// ---------------- f32x2 helpers ----------------
__device__ __forceinline__ uint64_t pk2(float lo, float hi) {
    uint64_t r; asm("mov.b64 %0, {%1, %2};" : "=l"(r) : "f"(lo), "f"(hi)); return r;
}
__device__ __forceinline__ void upk(uint64_t v, float& lo, float& hi) {
    asm("mov.b64 {%0, %1}, %2;" : "=f"(lo), "=f"(hi) : "l"(v));
}
__device__ __forceinline__ void fma2(uint64_t& d, uint64_t a, uint64_t b) {
    asm("fma.rn.f32x2 %0, %1, %2, %0;" : "+l"(d) : "l"(a), "l"(b));
}

// ---------------- zero state ----------------
__global__ void zero_state() {
    int n  = gridDim.x * blockDim.x;
    int i0 = blockIdx.x * blockDim.x + threadIdx.x;
    for (int i = i0; i < BB*3*32*32;   i += n) { g_v[i] = 0.f; g_s[i] = 0.f; }
    for (int i = i0; i < BB*64*32*32;  i += n)   g_m1[i] = 0.f;
    for (int i = i0; i < BB*128*16*16; i += n) { g_m2[i] = 0.f; g_m3[i] = 0.f; }
    for (int i = i0; i < BB*1024;      i += n) { g_m4[i] = 0.f; g_m5[i] = 0.f; }
    for (int i = i0; i < BB*10;        i += n)   g_mo[i] = 0.f;
}

// shifts ncu's "-s 5" window onto a conv_step launch
__global__ void nop_k() {}

// ---------------- per-step spike / threshold kernel ----------------
__global__ void __launch_bounds__(256) spike_step(const float* __restrict__ x) {
    int i = blockIdx.x * 256 + threadIdx.x;
    if (i == 0) g_tick = 0;                  // reset work queue for conv_step
    if (i < 49152) {
        float v = g_v[i] + x[i];
        v = v - g_s[i];
        g_v[i] = v;
        g_s[i] = (v > 1.0f) ? 1.0f : 0.0f;
    } else if (i < 311296) {
        int p  = i - 49152;                  // (B*64, 16, 16)
        int px = p & 15, py = (p >> 4) & 15, bc = p >> 8;
        int base = (bc*32 + py*2)*32 + px*2;
        float sum = 0.f;
        #pragma unroll
        for (int dy = 0; dy < 2; dy++)
            #pragma unroll
            for (int dx = 0; dx < 2; dx++) {
                int idx = base + dy*32 + dx;
                float o = (g_m1[idx] > 1.0f) ? 1.0f : 0.0f;
                g_o1[idx] = o;
                sum += o;
            }
        g_o1p[p] = sum * 0.25f;
    } else if (i < 835584) {
        int p = i - 311296;
        g_o2[p] = (g_m2[p] > 1.0f) ? 1.0f : 0.0f;
    } else if (i < 966656) {
        int p  = i - 835584;                 // (B*128, 8, 8)
        int px = p & 7, py = (p >> 3) & 7, bc = p >> 6;
        int base = (bc*16 + py*2)*16 + px*2;
        float sum = 0.f;
        #pragma unroll
        for (int dy = 0; dy < 2; dy++)
            #pragma unroll
            for (int dx = 0; dx < 2; dx++) {
                int idx = base + dy*16 + dx;
                float o = (g_m3[idx] > 1.0f) ? 1.0f : 0.0f;
                g_o3[idx] = o;
                sum += o;
            }
        int b = bc >> 7, c = bc & 127;
        g_f[b*8192 + c*64 + py*8 + px] = sum * 0.25f;
    } else if (i < 983040) {
        int p = i - 966656;
        g_o4[p] = (g_m4[p] > 1.0f) ? 1.0f : 0.0f;
    } else if (i < 999424) {
        int p = i - 983040;
        g_o5[p] = (g_m5[p] > 1.0f) ? 1.0f : 0.0f;
    }
}

// ---------------- conv band tile (16 oc, 8-row band, f32x2 inner) ----------------
// in: (B,CIN,16,16). thread tile: 2 oc x 4 px. 256 threads = 8 ocpairs x 8 rows x 4 xq.
// in_s: 16 ch x 10 rows x (20 + skew) floats, row skew +2*(row&1) kills LDS.64 conflicts.
// w_s: duplicated (w,w) pairs for direct warp-uniform LDS.64 broadcast.
__device__ __forceinline__ void conv_band(
    const float* __restrict__ in, const float* __restrict__ W,
    float* __restrict__ m, const float* __restrict__ osp,
    int CIN, int b, int oc0, int y0, float* sm)
{
    float* in_s = sm;                      // 16 * 204 = 3264
    float* w_s  = sm + 3264;               // 2304 pairs = 4608 floats
    const int tid = threadIdx.x;
    const int ol0 = (tid >> 5) * 2;        // oc pair (warp-uniform)
    const int sg  = tid & 31;
    const int yl  = sg & 7;                // local out row 0..7
    const int xb  = (sg >> 3) * 4;         // out col base {0,4,8,12}

    uint64_t acc[2][2];
    acc[0][0] = acc[0][1] = acc[1][0] = acc[1][1] = pk2(0.f, 0.f);

    for (int cb = 0; cb < CIN; cb += 16) {
        __syncthreads();
        for (int idx = tid; idx < 3200; idx += 256) {
            int c  = idx / 200; int r = idx - c*200;
            int yy = r / 20;    int xx = r - yy*20;
            int gy = y0 + yy - 1, gx = xx - 1;
            float v = 0.f;
            if ((unsigned)gy < 16u && (unsigned)gx < 16u)
                v = in[((b*CIN + cb + c)*16 + gy)*16 + gx];
            in_s[c*204 + yy*20 + 2*(yy & 1) + xx] = v;
        }
        for (int idx = tid; idx < 2304; idx += 256) {
            int ol = idx / 144; int t2 = idx - ol*144;
            float w = W[(oc0 + ol)*CIN*9 + cb*9 + t2];
            w_s[idx*2]     = w;
            w_s[idx*2 + 1] = w;
        }
        __syncthreads();
        const uint64_t* wsp = (const uint64_t*)w_s;
        #pragma unroll 1
        for (int c = 0; c < 16; c++) {
            const uint64_t* w0p = wsp + (ol0    )*144 + c*9;
            const uint64_t* w1p = wsp + (ol0 + 1)*144 + c*9;
            #pragma unroll
            for (int dy = 0; dy < 3; dy++) {
                int rr = yl + dy;
                const uint64_t* rp = (const uint64_t*)(in_s + c*204 + rr*20 + 2*(rr & 1) + xb);
                uint64_t E0 = rp[0], E1 = rp[1], E2 = rp[2];
                float a0,a1,a2,a3,a4,a5;
                upk(E0, a0, a1); upk(E1, a2, a3); upk(E2, a4, a5);
                uint64_t D0 = pk2(a1, a2), D1 = pk2(a3, a4);
                uint64_t W00 = w0p[dy*3+0], W01 = w0p[dy*3+1], W02 = w0p[dy*3+2];
                uint64_t W10 = w1p[dy*3+0], W11 = w1p[dy*3+1], W12 = w1p[dy*3+2];
                fma2(acc[0][0], E0, W00); fma2(acc[0][0], D0, W01); fma2(acc[0][0], E1, W02);
                fma2(acc[0][1], E1, W00); fma2(acc[0][1], D1, W01); fma2(acc[0][1], E2, W02);
                fma2(acc[1][0], E0, W10); fma2(acc[1][0], D0, W11); fma2(acc[1][0], E1, W12);
                fma2(acc[1][1], E1, W10); fma2(acc[1][1], D1, W11); fma2(acc[1][1], E2, W12);
            }
        }
    }
    #pragma unroll
    for (int q = 0; q < 2; q++) {
        int oc   = oc0 + ol0 + q;
        int base = ((b*128 + oc)*16 + (y0 + yl))*16 + xb;
        #pragma unroll
        for (int k = 0; k < 2; k++) {
            float a0, a1; upk(acc[q][k], a0, a1);
            int i0 = base + 2*k;
            m[i0]     = (m[i0]     + a0) - osp[i0];
            m[i0 + 1] = (m[i0 + 1] + a1) - osp[i0 + 1];
        }
    }
}

// ---------------- conv1 (3 in-ch, 32x32), 8 units per tile ----------------
__device__ __forceinline__ void conv1_tile(
    const float* __restrict__ s, const float* __restrict__ W1,
    float* __restrict__ m1, const float* __restrict__ o1,
    int tile, float* sm)
{
    int tid = threadIdx.x;
    for (int idx = tid; idx < 1728; idx += 256) sm[idx] = W1[idx];
    __syncthreads();
    #pragma unroll 1
    for (int u8 = 0; u8 < 8; u8++) {
        int u   = (tile*8 + u8)*256 + tid;
        int row = u >> 2;
        int xb  = (u & 3) * 8;
        int b   = row >> 11;
        int oc  = (row >> 5) & 63;
        int y   = row & 31;
        float acc[8];
        #pragma unroll
        for (int i = 0; i < 8; i++) acc[i] = 0.f;
        #pragma unroll
        for (int c = 0; c < 3; c++) {
            #pragma unroll
            for (int dy = 0; dy < 3; dy++) {
                int gy = y + dy - 1;
                if ((unsigned)gy >= 32u) continue;
                const float* srow = s + ((b*3 + c)*32 + gy)*32;
                float iv[10];
                #pragma unroll
                for (int t = 0; t < 10; t++) {
                    int gx = xb + t - 1;
                    iv[t] = ((unsigned)gx < 32u) ? srow[gx] : 0.f;
                }
                float w[3];
                #pragma unroll
                for (int dx = 0; dx < 3; dx++) w[dx] = sm[oc*27 + c*9 + dy*3 + dx];
                #pragma unroll
                for (int i = 0; i < 8; i++)
                    #pragma unroll
                    for (int dx = 0; dx < 3; dx++)
                        acc[i] += iv[i + dx] * w[dx];
            }
        }
        int base = ((b*64 + oc)*32 + y)*32 + xb;
        #pragma unroll
        for (int i = 0; i < 8; i++) {
            int idx = base + i;
            m1[idx] = (m1[idx] + acc[i]) - o1[idx];
        }
    }
}

// ---------------- FC tile: M[b,j] += A[b,:] . W[j,:] ----------------
__device__ __forceinline__ void fc_part(
    const float* __restrict__ A, const float* __restrict__ W,
    float* __restrict__ M, const float* __restrict__ O,
    int K, int J, int j0, int k0, int KS, bool subO, float* sm)
{
    float* fs = sm;          // [16][64]
    float* ws = sm + 1024;   // [64][65]
    int tid = threadIdx.x;
    int tj  = tid & 31;
    int tb  = tid >> 5;
    float acc[2][2] = {{0.f,0.f},{0.f,0.f}};
    for (int kc = k0; kc < k0 + KS; kc += 64) {
        __syncthreads();
        for (int idx = tid; idx < 1024; idx += 256) {
            int bb = idx >> 6, kk = idx & 63;
            fs[idx] = A[bb*K + kc + kk];
        }
        for (int idx = tid; idx < 4096; idx += 256) {
            int jl = idx >> 6, kk = idx & 63;
            ws[jl*65 + kk] = W[(j0 + jl)*K + kc + kk];
        }
        __syncthreads();
        #pragma unroll 4
        for (int kk = 0; kk < 64; kk++) {
            float w0 = ws[(tj*2    )*65 + kk];
            float w1 = ws[(tj*2 + 1)*65 + kk];
            float f0 = fs[ tb      *64 + kk];
            float f1 = fs[(tb + 8) *64 + kk];
            acc[0][0] += w0*f0;  acc[0][1] += w0*f1;
            acc[1][0] += w1*f0;  acc[1][1] += w1*f1;
        }
    }
    #pragma unroll
    for (int q = 0; q < 2; q++)
        #pragma unroll
        for (int r = 0; r < 2; r++) {
            int j  = j0 + tj*2 + q;
            int bb = tb + r*8;
            int idx = bb*J + j;
            float val = acc[q][r];
            if (subO) val -= O[idx];
            atomicAdd(&M[idx], val);
        }
}

// ---------------- fc3: mo += o5 @ L3^T ----------------
__device__ __forceinline__ void fc3_part(
    const float* __restrict__ o5, const float* __restrict__ L3, float* __restrict__ mo)
{
    int t = threadIdx.x;
    if (t >= 160) return;
    int b = t / 10, j = t - b*10;
    const float* a = o5 + b*1024;
    const float* w = L3 + j*1024;
    float acc = 0.f;
    #pragma unroll 4
    for (int k = 0; k < 1024; k++) acc += a[k]*w[k];
    mo[t] += acc;
}

// ---------------- fat per-step kernel with global work queue ----------------
// 657 near-uniform tiles, heavy first. Persistent blocks pull tickets so the
// GPU load-balances; per-tile outputs have a single deterministic writer
// (fc1 K-split keeps the previously-shipping atomic accumulation).
__global__ void __launch_bounds__(256) conv_step(
    const float* __restrict__ W1, const float* __restrict__ W2,
    const float* __restrict__ W3, const float* __restrict__ L1,
    const float* __restrict__ L2, const float* __restrict__ L3)
{
    __shared__ __align__(16) float sm[7872];
    __shared__ int s_tile;
    for (;;) {
        __syncthreads();
        if (threadIdx.x == 0) s_tile = atomicAdd(&g_tick, 1);
        __syncthreads();
        int t = s_tile;
        if (t >= NT) return;
        if (t < 256) {                      // conv3: b x ocg(16) x band(8 rows)
            int b = t >> 4, r = t & 15;
            conv_band(g_o2, W3, g_m3, g_o3, 128, b, (r >> 1)*16, (r & 1)*8, sm);
        } else if (t < 512) {               // conv2
            int i = t - 256;
            int b = i >> 4, r = i & 15;
            conv_band(g_o1p, W2, g_m2, g_o2, 64, b, (r >> 1)*16, (r & 1)*8, sm);
        } else if (t < 576) {               // fc1: 16 j-groups x K-split 4
            int i = t - 512;
            int ks = i >> 4, jg = i & 15;
            fc_part(g_f, L1, g_m4, g_o4, 8192, 1024, jg*64, ks*2048, 2048, ks == 0, sm);
        } else if (t < 592) {               // fc2
            int i = t - 576;
            fc_part(g_o4, L2, g_m5, g_o5, 1024, 1024, i*64, 0, 1024, true, sm);
        } else if (t < 656) {               // conv1: 64 tiles x 8 units
            conv1_tile(g_s, W1, g_m1, g_o1, t - 592, sm);
        } else {                            // fc3
            fc3_part(g_o5, L3, g_mo);
        }
    }
}

__global__ void write_out(float* __restrict__ out) {
    int t = threadIdx.x;
    if (t < 160) out[t] = g_mo[t];
}

extern "C" void kernel_launch(void* const* d_in, const int* in_sizes, int n_in,
                              void* d_out, int out_size)
{
    const float* x  = (const float*)d_in[0];
    const float* W1 = (const float*)d_in[1];
    const float* W2 = (const float*)d_in[2];
    const float* W3 = (const float*)d_in[3];
    const float* L1 = (const float*)d_in[4];
    const float* L2 = (const float*)d_in[5];
    const float* L3 = (const float*)d_in[6];

    zero_state<<<512, 256>>>();
    nop_k<<<1, 32>>>();      // aligns ncu -s 5 onto conv_step
    for (int t = 0; t < T_STEPS; t++) {
        spike_step<<<3904, 256>>>(x);
        conv_step<<<740, 256>>>(W1, W2, W3, L1, L2, L3);
    }
    write_out<<<1, 192>>>((float*)d_out);
}

// round 4
// speedup vs baseline: 1.8087x; 1.3165x over previous
#include <cuda_runtime.h>
#include <cstdint>

#define BB 16
#define T_STEPS 20
#define NT 3777
#define GRID_CONV 592

// ---------------- persistent device state ----------------
__device__ float g_v [BB*3*32*32];
__device__ float g_s [BB*3*32*32];
__device__ float g_m1[BB*64*32*32];
__device__ float g_o1[BB*64*32*32];
__device__ float g_o1p[BB*64*16*16];
__device__ float g_m2[BB*128*16*16];
__device__ float g_o2[BB*128*16*16];
__device__ float g_m3[BB*128*16*16];
__device__ float g_o3[BB*128*16*16];
__device__ float g_f [BB*8192];
__device__ float g_m4[BB*1024];
__device__ float g_o4[BB*1024];
__device__ float g_m5[BB*1024];
__device__ float g_o5[BB*1024];
__device__ float g_mo[BB*10];
__device__ int   g_tick;

// ---------------- partial-sum slabs (deterministic K-split) ----------------
__device__ float g_c1s[BB*64*32*32];        // conv1 raw out
__device__ float g_s2 [4][BB*128*16*16];    // conv2: 4 cin-splits
__device__ float g_s3 [8][BB*128*16*16];    // conv3: 8 cin-splits
__device__ float g_s4 [32][BB*1024];        // fc1: 32 k-splits
__device__ float g_s5 [4][BB*1024];         // fc2: 4 k-splits

// ---------------- f32x2 helpers ----------------
__device__ __forceinline__ uint64_t pk2(float lo, float hi) {
    uint64_t r; asm("mov.b64 %0, {%1, %2};" : "=l"(r) : "f"(lo), "f"(hi)); return r;
}
__device__ __forceinline__ void upk(uint64_t v, float& lo, float& hi) {
    asm("mov.b64 {%0, %1}, %2;" : "=f"(lo), "=f"(hi) : "l"(v));
}
__device__ __forceinline__ void fma2(uint64_t& d, uint64_t a, uint64_t b) {
    asm("fma.rn.f32x2 %0, %1, %2, %0;" : "+l"(d) : "l"(a), "l"(b));
}

// ---------------- zero state ----------------
__global__ void zero_state() {
    int n  = gridDim.x * blockDim.x;
    int i0 = blockIdx.x * blockDim.x + threadIdx.x;
    for (int i = i0; i < BB*3*32*32;   i += n) { g_v[i] = 0.f; g_s[i] = 0.f; }
    for (int i = i0; i < BB*64*32*32;  i += n) { g_m1[i] = 0.f; g_o1[i] = 0.f; g_c1s[i] = 0.f; }
    for (int i = i0; i < BB*128*16*16; i += n) {
        g_m2[i] = 0.f; g_o2[i] = 0.f; g_m3[i] = 0.f; g_o3[i] = 0.f;
        #pragma unroll
        for (int k = 0; k < 4; k++) g_s2[k][i] = 0.f;
        #pragma unroll
        for (int k = 0; k < 8; k++) g_s3[k][i] = 0.f;
    }
    for (int i = i0; i < BB*1024; i += n) {
        g_m4[i] = 0.f; g_o4[i] = 0.f; g_m5[i] = 0.f; g_o5[i] = 0.f;
        #pragma unroll
        for (int k = 0; k < 32; k++) g_s4[k][i] = 0.f;
        #pragma unroll
        for (int k = 0; k < 4;  k++) g_s5[k][i] = 0.f;
    }
    for (int i = i0; i < BB*10; i += n) g_mo[i] = 0.f;
}

// keeps ncu -s 5 aligned onto a conv_step launch
__global__ void nop_k() {}

// ---------------- per-step spike kernel: membrane completion + thresholds ----------------
// Completes step t-1's membrane updates (m = (m + sum(slabs)) - o_prev), then
// computes step t's spikes from the updated membranes. Fully deterministic.
__global__ void __launch_bounds__(256) spike_step(const float* __restrict__ x) {
    int i = blockIdx.x * 256 + threadIdx.x;
    if (i == 0) g_tick = 0;
    if (i < 49152) {
        float v = g_v[i] + x[i];
        v = v - g_s[i];
        g_v[i] = v;
        g_s[i] = (v > 1.0f) ? 1.0f : 0.0f;
    } else if (i < 311296) {
        int p  = i - 49152;                  // (B*64, 16, 16) pooled
        int px = p & 15, py = (p >> 4) & 15, bc = p >> 8;
        int base = (bc*32 + py*2)*32 + px*2;
        float sum = 0.f;
        #pragma unroll
        for (int dy = 0; dy < 2; dy++)
            #pragma unroll
            for (int dx = 0; dx < 2; dx++) {
                int idx = base + dy*32 + dx;
                float m = (g_m1[idx] + g_c1s[idx]) - g_o1[idx];
                float o = (m > 1.0f) ? 1.0f : 0.0f;
                g_m1[idx] = m;
                g_o1[idx] = o;
                sum += o;
            }
        g_o1p[p] = sum * 0.25f;
    } else if (i < 835584) {
        int p = i - 311296;
        float inp = ((g_s2[0][p] + g_s2[1][p]) + g_s2[2][p]) + g_s2[3][p];
        float m = (g_m2[p] + inp) - g_o2[p];
        g_m2[p] = m;
        g_o2[p] = (m > 1.0f) ? 1.0f : 0.0f;
    } else if (i < 966656) {
        int p  = i - 835584;                 // (B*128, 8, 8) pooled
        int px = p & 7, py = (p >> 3) & 7, bc = p >> 6;
        int base = (bc*16 + py*2)*16 + px*2;
        float sum = 0.f;
        #pragma unroll
        for (int dy = 0; dy < 2; dy++)
            #pragma unroll
            for (int dx = 0; dx < 2; dx++) {
                int idx = base + dy*16 + dx;
                float inp = 0.f;
                #pragma unroll
                for (int k = 0; k < 8; k++) inp += g_s3[k][idx];
                float m = (g_m3[idx] + inp) - g_o3[idx];
                float o = (m > 1.0f) ? 1.0f : 0.0f;
                g_m3[idx] = m;
                g_o3[idx] = o;
                sum += o;
            }
        int b = bc >> 7, c = bc & 127;
        g_f[b*8192 + c*64 + py*8 + px] = sum * 0.25f;
    } else if (i < 983040) {
        int p = i - 966656;
        float inp = 0.f;
        #pragma unroll 8
        for (int k = 0; k < 32; k++) inp += g_s4[k][p];
        float m = (g_m4[p] + inp) - g_o4[p];
        g_m4[p] = m;
        g_o4[p] = (m > 1.0f) ? 1.0f : 0.0f;
    } else if (i < 999424) {
        int p = i - 983040;
        float inp = ((g_s5[0][p] + g_s5[1][p]) + g_s5[2][p]) + g_s5[3][p];
        float m = (g_m5[p] + inp) - g_o5[p];
        g_m5[p] = m;
        g_o5[p] = (m > 1.0f) ? 1.0f : 0.0f;
    }
}

// ---------------- conv tile: 16 oc x 8 rows x 16 cols x 16 cin ----------------
// Pure producer: writes conv partial sums to slab (no membrane RMW).
// in_s rows skewed +6 floats on odd rows -> all LDS.64 conflict-free
// (half-warp 8B-unit indices tile {0..15} mod 16 for every dy / x-half).
__device__ __forceinline__ void conv_tile(
    const float* __restrict__ in, const float* __restrict__ W,
    float* __restrict__ slab, int CIN, int cb, int b, int oc0, int y0, float* sm)
{
    float* in_s = sm;                        // 16 ch * 208 = 3328 floats
    float* w_s  = sm + 3328;                 // 2304 dup pairs = 4608 floats
    const int tid = threadIdx.x;
    const int ol0 = (tid >> 5) * 2;          // warp-uniform oc pair
    const int sg  = tid & 31;
    const int yl  = sg & 7;                  // out row 0..7
    const int xb  = (sg >> 3) * 4;           // out col base {0,4,8,12}

    // fill input tile (rows yy=0..9 with halo), skewed pitch
    for (int idx = tid; idx < 3200; idx += 256) {
        int c  = idx / 200; int r = idx - c*200;
        int yy = r / 20;    int xx = r - yy*20;
        int gy = y0 + yy - 1, gx = xx - 1;
        float v = 0.f;
        if ((unsigned)gy < 16u && (unsigned)gx < 16u)
            v = in[((b*CIN + cb + c)*16 + gy)*16 + gx];
        in_s[c*208 + yy*20 + 6*(yy & 1) + xx] = v;
    }
    // fill duplicated weight pairs
    for (int idx = tid; idx < 2304; idx += 256) {
        int ol = idx / 144; int t2 = idx - ol*144;
        int c = t2 / 9, k = t2 - c*9;
        float w = W[(oc0 + ol)*CIN*9 + (cb + c)*9 + k];
        w_s[idx*2]     = w;
        w_s[idx*2 + 1] = w;
    }
    __syncthreads();

    uint64_t acc[2][2];
    acc[0][0] = acc[0][1] = acc[1][0] = acc[1][1] = pk2(0.f, 0.f);

    const int off0 =  yl     *20 + 6*( yl      & 1);
    const int off1 = (yl + 1)*20 + 6*((yl + 1) & 1);
    const int off2 = (yl + 2)*20 + 6*((yl + 2) & 1);
    const uint64_t* wsp = (const uint64_t*)w_s;

    #pragma unroll 1
    for (int c = 0; c < 16; c++) {
        const uint64_t* w0p = wsp + (ol0    )*144 + c*9;
        const uint64_t* w1p = wsp + (ol0 + 1)*144 + c*9;
        const float* bc0 = in_s + c*208 + xb;
        #pragma unroll
        for (int dy = 0; dy < 3; dy++) {
            const int off = (dy == 0) ? off0 : (dy == 1) ? off1 : off2;
            const uint64_t* rp = (const uint64_t*)(bc0 + off);
            uint64_t E0 = rp[0], E1 = rp[1], E2 = rp[2];
            float a0,a1,a2,a3,a4,a5;
            upk(E0, a0, a1); upk(E1, a2, a3); upk(E2, a4, a5);
            uint64_t D0 = pk2(a1, a2), D1 = pk2(a3, a4);
            uint64_t W00 = w0p[dy*3+0], W01 = w0p[dy*3+1], W02 = w0p[dy*3+2];
            uint64_t W10 = w1p[dy*3+0], W11 = w1p[dy*3+1], W12 = w1p[dy*3+2];
            fma2(acc[0][0], E0, W00); fma2(acc[0][0], D0, W01); fma2(acc[0][0], E1, W02);
            fma2(acc[0][1], E1, W00); fma2(acc[0][1], D1, W01); fma2(acc[0][1], E2, W02);
            fma2(acc[1][0], E0, W10); fma2(acc[1][0], D0, W11); fma2(acc[1][0], E1, W12);
            fma2(acc[1][1], E1, W10); fma2(acc[1][1], D1, W11); fma2(acc[1][1], E2, W12);
        }
    }
    #pragma unroll
    for (int q = 0; q < 2; q++) {
        int oc = oc0 + ol0 + q;
        float4 r;
        upk(acc[q][0], r.x, r.y);
        upk(acc[q][1], r.z, r.w);
        *(float4*)&slab[((b*128 + oc)*16 + (y0 + yl))*16 + xb] = r;
    }
}

// ---------------- conv1 tile (3 in-ch, 32x32), 4 units ----------------
__device__ __forceinline__ void conv1_tile(
    const float* __restrict__ s, const float* __restrict__ W1,
    float* __restrict__ slab, int tile, float* sm)
{
    int tid = threadIdx.x;
    for (int idx = tid; idx < 1728; idx += 256) sm[idx] = W1[idx];
    __syncthreads();
    #pragma unroll 1
    for (int u4 = 0; u4 < 4; u4++) {
        int u   = (tile*4 + u4)*256 + tid;
        int row = u >> 2;
        int xb  = (u & 3) * 8;
        int b   = row >> 11;
        int oc  = (row >> 5) & 63;
        int y   = row & 31;
        float acc[8];
        #pragma unroll
        for (int i = 0; i < 8; i++) acc[i] = 0.f;
        #pragma unroll
        for (int c = 0; c < 3; c++) {
            #pragma unroll
            for (int dy = 0; dy < 3; dy++) {
                int gy = y + dy - 1;
                if ((unsigned)gy >= 32u) continue;
                const float* srow = s + ((b*3 + c)*32 + gy)*32;
                float iv[10];
                #pragma unroll
                for (int t = 0; t < 10; t++) {
                    int gx = xb + t - 1;
                    iv[t] = ((unsigned)gx < 32u) ? srow[gx] : 0.f;
                }
                float w[3];
                #pragma unroll
                for (int dx = 0; dx < 3; dx++) w[dx] = sm[oc*27 + c*9 + dy*3 + dx];
                #pragma unroll
                for (int i = 0; i < 8; i++)
                    #pragma unroll
                    for (int dx = 0; dx < 3; dx++)
                        acc[i] += iv[i + dx] * w[dx];
            }
        }
        int base = ((b*64 + oc)*32 + y)*32 + xb;
        #pragma unroll
        for (int i = 0; i < 8; i++) slab[base + i] = acc[i];
    }
}

// ---------------- FC tile: out[b,j] = A[b,k0:k0+256] . W[j,k0:k0+256] ----------------
__device__ __forceinline__ void fc_tile(
    const float* __restrict__ A, const float* __restrict__ W,
    float* __restrict__ out, int K, int j0, int k0, float* sm)
{
    float* fs = sm;          // [16][64]
    float* ws = sm + 1024;   // [64][65]
    int tid = threadIdx.x;
    int tj  = tid & 31;
    int tb  = tid >> 5;
    float acc[2][2] = {{0.f,0.f},{0.f,0.f}};
    #pragma unroll 1
    for (int kc = k0; kc < k0 + 256; kc += 64) {
        __syncthreads();
        for (int idx = tid; idx < 1024; idx += 256) {
            int bb = idx >> 6, kk = idx & 63;
            fs[idx] = A[bb*K + kc + kk];
        }
        for (int idx = tid; idx < 4096; idx += 256) {
            int jl = idx >> 6, kk = idx & 63;
            ws[jl*65 + kk] = W[(j0 + jl)*K + kc + kk];
        }
        __syncthreads();
        #pragma unroll 4
        for (int kk = 0; kk < 64; kk++) {
            float w0 = ws[(tj*2    )*65 + kk];
            float w1 = ws[(tj*2 + 1)*65 + kk];
            float f0 = fs[ tb      *64 + kk];
            float f1 = fs[(tb + 8) *64 + kk];
            acc[0][0] += w0*f0;  acc[0][1] += w0*f1;
            acc[1][0] += w1*f0;  acc[1][1] += w1*f1;
        }
    }
    #pragma unroll
    for (int q = 0; q < 2; q++)
        #pragma unroll
        for (int r = 0; r < 2; r++)
            out[(tb + r*8)*1024 + (j0 + tj*2 + q)] = acc[q][r];
}

// ---------------- fc3: mo += o5 @ L3^T (single block, deterministic) ----------------
__device__ __forceinline__ void fc3_part(
    const float* __restrict__ o5, const float* __restrict__ L3, float* __restrict__ mo)
{
    int t = threadIdx.x;
    if (t >= 160) return;
    int b = t / 10, j = t - b*10;
    const float* a = o5 + b*1024;
    const float* w = L3 + j*1024;
    float acc = 0.f;
    #pragma unroll 4
    for (int k = 0; k < 1024; k++) acc += a[k]*w[k];
    mo[t] += acc;
}

// ---------------- fat per-step kernel: work queue over 3777 uniform tiles ----------------
__global__ void __launch_bounds__(256, 4) conv_step(
    const float* __restrict__ W1, const float* __restrict__ W2,
    const float* __restrict__ W3, const float* __restrict__ L1,
    const float* __restrict__ L2, const float* __restrict__ L3)
{
    __shared__ __align__(16) float sm[7936];
    __shared__ int s_tile;
    for (;;) {
        __syncthreads();
        if (threadIdx.x == 0) s_tile = atomicAdd(&g_tick, 1);
        __syncthreads();
        int t = s_tile;
        if (t >= NT) return;
        if (t == 0) {
            fc3_part(g_o5, L3, g_mo);
        } else if (t < 2049) {               // conv3: 16b x 8ocg x 2yb x 8ks
            int i = t - 1;
            int ks = i & 7, yb = (i >> 3) & 1, ocg = (i >> 4) & 7, b = i >> 7;
            conv_tile(g_o2, W3, &g_s3[ks][0], 128, ks*16, b, ocg*16, yb*8, sm);
        } else if (t < 3073) {               // conv2: 16b x 8ocg x 2yb x 4ks
            int i = t - 2049;
            int ks = i & 3, yb = (i >> 2) & 1, ocg = (i >> 3) & 7, b = i >> 6;
            conv_tile(g_o1p, W2, &g_s2[ks][0], 64, ks*16, b, ocg*16, yb*8, sm);
        } else if (t < 3585) {               // fc1: 16jg x 32ks
            int i = t - 3073;
            int jg = i & 15, ks = i >> 4;
            fc_tile(g_f, L1, &g_s4[ks][0], 8192, jg*64, ks*256, sm);
        } else if (t < 3713) {               // conv1: 128 tiles x 4 units
            conv1_tile(g_s, W1, g_c1s, t - 3585, sm);
        } else {                             // fc2: 16jg x 4ks
            int i = t - 3713;
            int jg = i & 15, ks = i >> 4;
            fc_tile(g_o4, L2, &g_s5[ks][0], 1024, jg*64, ks*256, sm);
        }
    }
}

__global__ void write_out(float* __restrict__ out) {
    int t = threadIdx.x;
    if (t < 160) out[t] = g_mo[t];
}

extern "C" void kernel_launch(void* const* d_in, const int* in_sizes, int n_in,
                              void* d_out, int out_size)
{
    const float* x  = (const float*)d_in[0];
    const float* W1 = (const float*)d_in[1];
    const float* W2 = (const float*)d_in[2];
    const float* W3 = (const float*)d_in[3];
    const float* L1 = (const float*)d_in[4];
    const float* L2 = (const float*)d_in[5];
    const float* L3 = (const float*)d_in[6];

    zero_state<<<512, 256>>>();
    nop_k<<<1, 32>>>();
    for (int t = 0; t < T_STEPS; t++) {
        spike_step<<<3904, 256>>>(x);
        conv_step<<<GRID_CONV, 256>>>(W1, W2, W3, L1, L2, L3);
    }
    write_out<<<1, 192>>>((float*)d_out);
}